// round 17
// baseline (speedup 1.0000x reference)
#include <cuda_runtime.h>
#include <cuda_fp16.h>

// Problem constants
#define NW 16384   // words
#define WL 16      // word length
#define D  300     // hidden dim
#define DP 320     // padded channel count (zeros in [300,320))
#define NL 128     // letters
#define KS 3       // conv taps

// Encode config (frozen at the measured 26.1 us form)
#define WPB 24
#define ENC_THREADS 768
#define B0 118
#define B1 118
#define B2 60
#define ENC_BLOCKS (B0 + B1 + B2)           // 296 = 2 CTA/SM * 148 SMs
#define ENC_SMEM (KS * NL * 128 * 2)        // 96 KB

// Prep: ONE launch, 96 blocks x 768 threads (all co-resident; <=148 SMs).
//  [0,20):  transpose emb -> embT (2 tiles each; 40 tiles total) then flag++
//  [20,42): pack words (22 * 768 = 16896 >= 16384)
//  [42,96): P build, 6 channels each (54 * 6 = 324 >= 320); waits on flag
#define PREP_THREADS 768
#define TRB 20
#define PKB0 20
#define PKB1 42
#define PB0 42
#define NPB 54
#define PREP_BLOCKS 96

// Device scratch
__device__ __half g_Ph[KS][NL][DP];  // per-letter conv partials (bias in k=1 tap)
__device__ float  g_embT[D * NL];    // emb transposed: [i][v]
__device__ uint4  g_wpk[NW];         // packed letters: 16 u8 per word

// Producer->consumer flags (replay-safe: last P block resets both)
__device__ unsigned g_tflag = 0;     // transpose blocks done
__device__ unsigned g_pdone = 0;     // P blocks past their wait

// ---------------------------------------------------------------------------
// Kernel 1: fused prep with intra-launch transpose->P pipeline.
// ---------------------------------------------------------------------------
__global__ __launch_bounds__(PREP_THREADS) void prep_kernel(const int* __restrict__ words,
                                                            const float* __restrict__ emb,
                                                            const float* __restrict__ w,
                                                            const float* __restrict__ bias) {
    __shared__ __align__(16) float sm[6 * KS * 304];  // 21.9 KB, aliased per role
    const int b   = blockIdx.x;
    const int tid = threadIdx.x;

    if (b < TRB) {
        // ---- transpose: 2 tiles of 32i x 32v per block ----
        float (*t)[32][33] = (float (*)[32][33])sm;   // [2][32][33]
        const int g  = tid >> 8;         // 0..2 (group 2 idles)
        const int tl = tid & 255;
        const int x  = tl & 31, y = tl >> 5;  // 32 x 8
        const int tnum = 2 * b + g;
        if (g < 2) {
            const int bx = tnum % 10, by = tnum / 10;
            const int i0 = bx * 32, v0 = by * 32;
#pragma unroll
            for (int dy = 0; dy < 32; dy += 8) {
                int v = v0 + y + dy, i = i0 + x;
                t[g][y + dy][x] = (i < D) ? emb[v * D + i] : 0.f;
            }
        }
        __syncthreads();
        if (g < 2) {
            const int bx = tnum % 10, by = tnum / 10;
            const int i0 = bx * 32, v0 = by * 32;
#pragma unroll
            for (int dy = 0; dy < 32; dy += 8) {
                int i = i0 + y + dy, v = v0 + x;
                if (i < D) g_embT[i * NL + v] = t[g][x][y + dy];
            }
        }
        __syncthreads();
        if (tid == 0) {
            __threadfence();              // publish embT
            atomicAdd(&g_tflag, 1u);
        }
    } else if (b < PKB1) {
        // ---- pack words ----
        const int n = (b - PKB0) * PREP_THREADS + tid;
        if (n < NW) {
            unsigned r0 = 0, r1 = 0, r2 = 0, r3 = 0;
#pragma unroll
            for (int l = 0; l < 4; ++l)  r0 |= ((unsigned)words[l * NW + n] & 0xFF) << (l * 8);
#pragma unroll
            for (int l = 4; l < 8; ++l)  r1 |= ((unsigned)words[l * NW + n] & 0xFF) << ((l - 4) * 8);
#pragma unroll
            for (int l = 8; l < 12; ++l) r2 |= ((unsigned)words[l * NW + n] & 0xFF) << ((l - 8) * 8);
#pragma unroll
            for (int l = 12; l < 16; ++l) r3 |= ((unsigned)words[l * NW + n] & 0xFF) << ((l - 12) * 8);
            g_wpk[n] = make_uint4(r0, r1, r2, r3);
        }
    } else {
        // ---- P build: 6 channels x 128 letters; waits for embT ----
        const int ob = (b - PB0) * 6;
        const int j  = tid >> 7;        // 0..5 (channel within block)
        const int v  = tid & 127;       // letter
        const int o  = ob + j;

        // Stage w rows de-interleaved (overlaps the transpose blocks' work)
        for (int t = tid; t < 6 * D * KS; t += PREP_THREADS) {
            int jj = t / (D * KS), r = t % (D * KS);
            int oo = ob + jj;
            sm[(jj * KS + r % 3) * 304 + r / 3] = (oo < D) ? w[oo * D * KS + r] : 0.f;
        }
        __syncthreads();

        // Wait for all 20 transpose blocks (54 pollers only — no storm)
        if (tid == 0) {
            while (*(volatile unsigned*)&g_tflag < (unsigned)TRB) __nanosleep(64);
            __threadfence();              // acquire embT
        }
        __syncthreads();

        float a0 = 0.f, a1 = 0.f, a2 = 0.f;
        if (o < D) {
            const float* et  = g_embT + v;   // stride NL, coalesced (lane = v)
            const float* w0p = sm + (j * KS + 0) * 304;
            const float* w1p = sm + (j * KS + 1) * 304;
            const float* w2p = sm + (j * KS + 2) * 304;
#pragma unroll 5
            for (int i = 0; i < D; i += 4) {
                float4 w0 = *(const float4*)(w0p + i);
                float4 w1 = *(const float4*)(w1p + i);
                float4 w2 = *(const float4*)(w2p + i);
                float e0 = __ldg(et + (i + 0) * NL);
                float e1 = __ldg(et + (i + 1) * NL);
                float e2 = __ldg(et + (i + 2) * NL);
                float e3 = __ldg(et + (i + 3) * NL);
                a0 = fmaf(e0, w0.x, a0); a1 = fmaf(e0, w1.x, a1); a2 = fmaf(e0, w2.x, a2);
                a0 = fmaf(e1, w0.y, a0); a1 = fmaf(e1, w1.y, a1); a2 = fmaf(e1, w2.y, a2);
                a0 = fmaf(e2, w0.z, a0); a1 = fmaf(e2, w1.z, a1); a2 = fmaf(e2, w2.z, a2);
                a0 = fmaf(e3, w0.w, a0); a1 = fmaf(e3, w1.w, a1); a2 = fmaf(e3, w2.w, a2);
            }
        }
        if (o < DP) {
            bool real = (o < D);
            float bv = real ? bias[o] : 0.f;
            g_Ph[0][v][o] = __float2half(real ? a0 : 0.f);
            g_Ph[1][v][o] = __float2half(real ? (a1 + bv) : 0.f);  // bias in k=1
            g_Ph[2][v][o] = __float2half(real ? a2 : 0.f);
        }

        // Replay-safe flag reset: last P block past the wait clears both.
        __syncthreads();
        if (tid == 0) {
            unsigned d = atomicAdd(&g_pdone, 1u);
            if (d == (unsigned)(NPB - 1)) {
                g_pdone = 0;
                __threadfence();
                g_tflag = 0;
            }
        }
    }
}

// ---------------------------------------------------------------------------
// Kernel 2: encode — byte-identical to the measured 26.1 us round-16 kernel.
// Rolling-address inner loop; tap tables at smem offsets 0/32768/65536.
// ---------------------------------------------------------------------------
#define GETL(l) ((lw[(l) >> 2] >> (((l) & 3) * 8)) & 0xFF)

#define INNER_BODY(LOB)                                                          \
    half2 m0 = NEGI, m1 = NEGI, m2 = NEGI, m3 = NEGI;                            \
    {                                                                            \
        const char* Pb = (const char*)Pv;                                        \
        unsigned a0p = 0;                                                        \
        unsigned a1p = (lw[0] & 0xFF) * 256 + (LOB);                             \
        _Pragma("unroll")                                                        \
        for (int l = 0; l < WL; ++l) {                                           \
            unsigned a2p = (l < WL - 1) ? GETL(l + 1) * 256 + (LOB) : 0;         \
            uint4 a = *(const uint4*)(Pb + 32768 + a1p);  /* k=1, this char */   \
            half2 h0 = *(half2*)&a.x, h1 = *(half2*)&a.y;                        \
            half2 h2 = *(half2*)&a.z, h3 = *(half2*)&a.w;                        \
            if (l > 0) {                                                         \
                uint4 q = *(const uint4*)(Pb + a0p);       /* k=0, prev */       \
                h0 = __hadd2(h0, *(half2*)&q.x); h1 = __hadd2(h1, *(half2*)&q.y);\
                h2 = __hadd2(h2, *(half2*)&q.z); h3 = __hadd2(h3, *(half2*)&q.w);\
            }                                                                    \
            if (l < WL - 1) {                                                    \
                uint4 q = *(const uint4*)(Pb + 65536 + a2p); /* k=2, next */     \
                h0 = __hadd2(h0, *(half2*)&q.x); h1 = __hadd2(h1, *(half2*)&q.y);\
                h2 = __hadd2(h2, *(half2*)&q.z); h3 = __hadd2(h3, *(half2*)&q.w);\
            }                                                                    \
            m0 = __hmax2(m0, h0); m1 = __hmax2(m1, h1);                          \
            m2 = __hmax2(m2, h2); m3 = __hmax2(m3, h3);                          \
            a0p = a1p; a1p = a2p;                                                \
        }                                                                        \
    }

__global__ __launch_bounds__(ENC_THREADS, 2) void encode_kernel(float* __restrict__ out) {
    extern __shared__ uint4 Pv[];  // [KS*NL rows][16 uint4], row stride 256 B

    int b = blockIdx.x;
    int slice, lb, nb;
    if (b < B0)           { slice = 0; lb = b;           nb = B0; }
    else if (b < B0 + B1) { slice = 1; lb = b - B0;      nb = B1; }
    else                  { slice = 2; lb = b - B0 - B1; nb = B2; }
    const int c0 = slice * 128;
    const int nchunk = (slice == 2) ? 8 : 16;  // valid uint4 chunks per row

    const uint4* gP = (const uint4*)g_Ph;  // row stride DP/8 = 40 uint4
    for (int idx = threadIdx.x; idx < KS * NL * nchunk; idx += ENC_THREADS) {
        int r = idx / nchunk, c = idx % nchunk;
        Pv[r * 16 + c] = gP[r * (DP / 8) + slice * 16 + c];
    }
    __syncthreads();

    const int lane  = threadIdx.x & 31;
    const int wid   = threadIdx.x >> 5;
    const int wsl   = lb * WPB + wid;
    const int nwarp = nb * WPB;

    const __half NH = __ushort_as_half((unsigned short)0xFC00);  // -inf
    const half2 NEGI = __halves2half2(NH, NH);

    if (slice < 2) {
        // ---- 128-ch slice: 2 words per warp (16-lane halves) ----
        const int lo   = lane & 15;
        const int half = lane >> 4;
        const int ch   = c0 + lo * 8;
        const unsigned LOB = lo * 16;   // byte offset within row

        uint4 pk = g_wpk[2 * wsl + half];
        for (int p = wsl; p < NW / 2; p += nwarp) {
            const int pn = p + nwarp;
            uint4 nxt = make_uint4(0, 0, 0, 0);
            if (pn < NW / 2) nxt = g_wpk[2 * pn + half];

            unsigned lw[4] = {pk.x, pk.y, pk.z, pk.w};
            const int gw = 2 * p + half;

            INNER_BODY(LOB)

            float2 f0 = __half22float2(m0), f1 = __half22float2(m1);
            float2 f2 = __half22float2(m2), f3 = __half22float2(m3);
            float* op = out + (size_t)gw * D + ch;
            float4 r;
            r.x = fmaxf(f0.x, 0.f); r.y = fmaxf(f0.y, 0.f);
            r.z = fmaxf(f1.x, 0.f); r.w = fmaxf(f1.y, 0.f);
            *(float4*)op = r;
            r.x = fmaxf(f2.x, 0.f); r.y = fmaxf(f2.y, 0.f);
            r.z = fmaxf(f3.x, 0.f); r.w = fmaxf(f3.y, 0.f);
            *(float4*)(op + 4) = r;

            pk = nxt;
        }
    } else {
        // ---- 64-ch slice (channels 256..299 real): 4 words per warp ----
        const int lo8 = lane & 7;
        const int g   = lane >> 3;
        const int ch  = c0 + lo8 * 8;  // 256..312
        const unsigned LOB = lo8 * 16;

        uint4 pk = g_wpk[4 * wsl + g];
        for (int p = wsl; p < NW / 4; p += nwarp) {
            const int pn = p + nwarp;
            uint4 nxt = make_uint4(0, 0, 0, 0);
            if (pn < NW / 4) nxt = g_wpk[4 * pn + g];

            unsigned lw[4] = {pk.x, pk.y, pk.z, pk.w};
            const int gw = 4 * p + g;

            INNER_BODY(LOB)

            float2 f0 = __half22float2(m0), f1 = __half22float2(m1);
            float2 f2 = __half22float2(m2), f3 = __half22float2(m3);
            float* op = out + (size_t)gw * D + ch;
            if (ch < D) {
                float4 r;
                r.x = fmaxf(f0.x, 0.f); r.y = fmaxf(f0.y, 0.f);
                r.z = fmaxf(f1.x, 0.f); r.w = fmaxf(f1.y, 0.f);
                *(float4*)op = r;
            }
            if (ch + 4 < D) {
                float4 r;
                r.x = fmaxf(f2.x, 0.f); r.y = fmaxf(f2.y, 0.f);
                r.z = fmaxf(f3.x, 0.f); r.w = fmaxf(f3.y, 0.f);
                *(float4*)(op + 4) = r;
            }
            pk = nxt;
        }
    }
}

// ---------------------------------------------------------------------------
// Launch. Inputs: words(int32), emb(f32), conv_w(f32), conv_b(f32). Out f32.
// ---------------------------------------------------------------------------
extern "C" void kernel_launch(void* const* d_in, const int* in_sizes, int n_in,
                              void* d_out, int out_size) {
    const int*   words = (const int*)d_in[0];
    const float* emb   = (const float*)d_in[1];
    const float* w     = (const float*)d_in[2];
    const float* b     = (const float*)d_in[3];
    float*       out   = (float*)d_out;

    prep_kernel<<<PREP_BLOCKS, PREP_THREADS>>>(words, emb, w, b);

    cudaFuncSetAttribute(encode_kernel,
                         cudaFuncAttributeMaxDynamicSharedMemorySize, ENC_SMEM);
    encode_kernel<<<ENC_BLOCKS, ENC_THREADS, ENC_SMEM>>>(out);
}